// round 1
// baseline (speedup 1.0000x reference)
#include <cuda_runtime.h>
#include <math.h>

#define HW 4096
#define CH 256
#define NB 4
#define NBC (NB*CH)        // 1024

// ---- scratch (static device globals; no allocation) ----
__device__ float g_mean[2 * NBC];
__device__ float g_rstd[2 * NBC];
__device__ float g_Q[(size_t)NB * HW * CH];
__device__ float g_K[(size_t)NB * HW * CH];
__device__ float g_V[(size_t)NB * HW * CH];

// =====================================================================
// Stage 1: per-(b,c) mean / rstd for content (idx 0..1023) and style
// (idx 1024..2047). var is unbiased (ddof=1), +1e-5 inside sqrt.
// =====================================================================
__global__ void stats_kernel(const float* __restrict__ content,
                             const float* __restrict__ style) {
    int id = blockIdx.x;                              // 0..2047
    const float* base = (id < NBC ? content : style) + (size_t)(id & (NBC - 1)) * HW;
    float s = 0.f, s2 = 0.f;
    const float4* b4 = (const float4*)base;
    for (int i = threadIdx.x; i < HW / 4; i += 256) {
        float4 v = b4[i];
        s  += v.x + v.y + v.z + v.w;
        s2 += v.x * v.x + v.y * v.y + v.z * v.z + v.w * v.w;
    }
    #pragma unroll
    for (int o = 16; o; o >>= 1) {
        s  += __shfl_xor_sync(~0u, s, o);
        s2 += __shfl_xor_sync(~0u, s2, o);
    }
    __shared__ float sh[8][2];
    int w = threadIdx.x >> 5, l = threadIdx.x & 31;
    if (l == 0) { sh[w][0] = s; sh[w][1] = s2; }
    __syncthreads();
    if (threadIdx.x == 0) {
        s = 0.f; s2 = 0.f;
        #pragma unroll
        for (int i = 0; i < 8; i++) { s += sh[i][0]; s2 += sh[i][1]; }
        float m   = s / (float)HW;
        float var = (s2 - (float)HW * m * m) / (float)(HW - 1);
        g_mean[id] = m;
        g_rstd[id] = rsqrtf(var + 1e-5f);
    }
}

// =====================================================================
// Stage 2: Q/K/V GEMMs. Out[p][o] = sum_c W[o][c] * Xn[c][p] + bias[o]
// Xn is normalized on load (identity for V). Block tile 128p x 64o,
// 256 threads, 8x4 micro-tile, k-chunks of 32.
// =====================================================================
__global__ __launch_bounds__(256) void qkv_gemm(
    const float* __restrict__ content, const float* __restrict__ style,
    const float* __restrict__ Wf, const float* __restrict__ bf,
    const float* __restrict__ Wg, const float* __restrict__ bg,
    const float* __restrict__ Wh, const float* __restrict__ bh)
{
    int z   = blockIdx.z;
    int mat = z % 3, b = z / 3;
    const float *X, *W, *bias;
    float* out;
    int soff;
    if (mat == 0)      { X = content; W = Wf; bias = bf; soff = 0;   out = g_Q; }
    else if (mat == 1) { X = style;   W = Wg; bias = bg; soff = NBC; out = g_K; }
    else               { X = style;   W = Wh; bias = bh; soff = -1;  out = g_V; }
    X   += (size_t)b * CH * HW;
    out += (size_t)b * HW * CH;
    int p0 = blockIdx.x * 128, o0 = blockIdx.y * 64;

    __shared__ float Xs[32][132];   // [channel][pixel], padded
    __shared__ float Ws[64][36];    // [o][channel], padded

    int tid = threadIdx.x;
    int tx  = tid & 15, ty = tid >> 4;    // tx -> pixel octet, ty -> o quad
    float acc[8][4];
    #pragma unroll
    for (int u = 0; u < 8; u++)
        #pragma unroll
        for (int v = 0; v < 4; v++) acc[u][v] = 0.f;

    for (int c0 = 0; c0 < CH; c0 += 32) {
        __syncthreads();
        // X tile (normalized)
        #pragma unroll
        for (int r = 0; r < 4; r++) {
            int e = tid + 256 * r;                 // 0..1023 float4 units
            int row = e >> 5, c4 = e & 31;
            float4 v = *(const float4*)(X + (size_t)(c0 + row) * HW + p0 + c4 * 4);
            if (soff >= 0) {
                float m  = g_mean[soff + b * CH + c0 + row];
                float rs = g_rstd[soff + b * CH + c0 + row];
                v.x = (v.x - m) * rs; v.y = (v.y - m) * rs;
                v.z = (v.z - m) * rs; v.w = (v.w - m) * rs;
            }
            *(float4*)&Xs[row][c4 * 4] = v;
        }
        // W tile
        #pragma unroll
        for (int r = 0; r < 2; r++) {
            int e = tid + 256 * r;                 // 0..511 float4 units
            int row = e >> 3, c4 = e & 7;
            *(float4*)&Ws[row][c4 * 4] =
                *(const float4*)(W + (size_t)(o0 + row) * CH + c0 + c4 * 4);
        }
        __syncthreads();
        #pragma unroll
        for (int cc = 0; cc < 32; cc++) {
            float4 x0 = *(float4*)&Xs[cc][tx * 8];
            float4 x1 = *(float4*)&Xs[cc][tx * 8 + 4];
            float w0 = Ws[ty * 4 + 0][cc], w1 = Ws[ty * 4 + 1][cc];
            float w2 = Ws[ty * 4 + 2][cc], w3 = Ws[ty * 4 + 3][cc];
            float xv[8] = {x0.x, x0.y, x0.z, x0.w, x1.x, x1.y, x1.z, x1.w};
            #pragma unroll
            for (int u = 0; u < 8; u++) {
                acc[u][0] += xv[u] * w0;
                acc[u][1] += xv[u] * w1;
                acc[u][2] += xv[u] * w2;
                acc[u][3] += xv[u] * w3;
            }
        }
    }
    float b0 = bias[o0 + ty * 4 + 0], b1 = bias[o0 + ty * 4 + 1];
    float b2 = bias[o0 + ty * 4 + 2], b3 = bias[o0 + ty * 4 + 3];
    #pragma unroll
    for (int u = 0; u < 8; u++) {
        float4 ov = make_float4(acc[u][0] + b0, acc[u][1] + b1,
                                acc[u][2] + b2, acc[u][3] + b3);
        *(float4*)(out + (size_t)(p0 + tx * 8 + u) * CH + o0 + ty * 4) = ov;
    }
}

// =====================================================================
// Stage 3: fused flash attention + moments + AdaAttN epilogue.
// 256 threads, M=64 queries/block, N=64 keys/tile, d=256.
// Each warp owns 8 query rows end-to-end (softmax is warp-local).
// Each lane owns an 8-channel slice of the output accumulators.
// =====================================================================
#define MQ   64
#define NT   64
#define QPAD 260
#define PPAD 68

__global__ __launch_bounds__(256, 1) void attn_kernel(
    const float* __restrict__ content, float* __restrict__ out)
{
    extern __shared__ float sm[];
    float* Qs = sm;                       // MQ * QPAD
    float* Ks = Qs + MQ * QPAD;           // NT * QPAD
    float* Vs = Ks + NT * QPAD;           // NT * QPAD
    float* Ps = Vs + NT * QPAD;           // MQ * PPAD

    int b  = blockIdx.y;
    int p0 = blockIdx.x * MQ;
    int tid  = threadIdx.x;
    int wid  = tid >> 5, lane = tid & 31;
    int tx   = tid & 15, ty = tid >> 4;
    int i0   = ty * 4, j0 = tx * 4;       // warp `wid` owns rows 8*wid..8*wid+7
    int d0   = lane * 8;                  // channel slice per lane

    // load Q tile
    const float4* Qg = (const float4*)(g_Q + ((size_t)b * HW + p0) * CH);
    #pragma unroll
    for (int r = 0; r < 16; r++) {
        int e = tid + 256 * r;            // 0..4095 float4 units
        int row = e >> 6, c4 = e & 63;
        *(float4*)&Qs[row * QPAD + c4 * 4] = Qg[row * 64 + c4];
    }

    float O1[8][8], O2[8][8];
    #pragma unroll
    for (int rr = 0; rr < 8; rr++)
        #pragma unroll
        for (int u = 0; u < 8; u++) { O1[rr][u] = 0.f; O2[rr][u] = 0.f; }
    float mrow[8], lrow[8];
    #pragma unroll
    for (int rr = 0; rr < 8; rr++) { mrow[rr] = -1e30f; lrow[rr] = 0.f; }

    for (int kt = 0; kt < HW / NT; kt++) {
        __syncthreads();   // protect Ks/Vs/Ps from previous tile's readers
        const float4* Kg = (const float4*)(g_K + ((size_t)b * HW + kt * NT) * CH);
        const float4* Vg = (const float4*)(g_V + ((size_t)b * HW + kt * NT) * CH);
        #pragma unroll
        for (int r = 0; r < 16; r++) {
            int e = tid + 256 * r;
            int row = e >> 6, c4 = e & 63;
            *(float4*)&Ks[row * QPAD + c4 * 4] = Kg[row * 64 + c4];
            *(float4*)&Vs[row * QPAD + c4 * 4] = Vg[row * 64 + c4];
        }
        __syncthreads();

        // ---- scores: 4x4 per thread ----
        float s[4][4];
        #pragma unroll
        for (int ii = 0; ii < 4; ii++)
            #pragma unroll
            for (int jj = 0; jj < 4; jj++) s[ii][jj] = 0.f;

        #pragma unroll 2
        for (int k = 0; k < CH; k += 4) {
            float4 q[4], kk[4];
            #pragma unroll
            for (int ii = 0; ii < 4; ii++)
                q[ii] = *(const float4*)&Qs[(i0 + ii) * QPAD + k];
            #pragma unroll
            for (int jj = 0; jj < 4; jj++)
                kk[jj] = *(const float4*)&Ks[(j0 + jj) * QPAD + k];
            #pragma unroll
            for (int ii = 0; ii < 4; ii++)
                #pragma unroll
                for (int jj = 0; jj < 4; jj++)
                    s[ii][jj] += q[ii].x * kk[jj].x + q[ii].y * kk[jj].y +
                                 q[ii].z * kk[jj].z + q[ii].w * kk[jj].w;
        }
        #pragma unroll
        for (int ii = 0; ii < 4; ii++)
            #pragma unroll
            for (int jj = 0; jj < 4; jj++)
                Ps[(i0 + ii) * PPAD + j0 + jj] = s[ii][jj];
        __syncwarp();      // Ps rows 8*wid..+7 are written only by this warp

        // ---- warp-local online softmax over this warp's 8 rows ----
        #pragma unroll
        for (int rr = 0; rr < 8; rr++) {
            int r = wid * 8 + rr;
            float s0 = Ps[r * PPAD + lane];
            float s1 = Ps[r * PPAD + 32 + lane];
            float mx = fmaxf(s0, s1);
            #pragma unroll
            for (int o = 16; o; o >>= 1) mx = fmaxf(mx, __shfl_xor_sync(~0u, mx, o));
            float mnew = fmaxf(mrow[rr], mx);
            float corr = __expf(mrow[rr] - mnew);
            float e0 = __expf(s0 - mnew);
            float e1 = __expf(s1 - mnew);
            float rs = e0 + e1;
            #pragma unroll
            for (int o = 16; o; o >>= 1) rs += __shfl_xor_sync(~0u, rs, o);
            lrow[rr] = lrow[rr] * corr + rs;
            mrow[rr] = mnew;
            Ps[r * PPAD + lane]      = e0;
            Ps[r * PPAD + 32 + lane] = e1;
            #pragma unroll
            for (int u = 0; u < 8; u++) { O1[rr][u] *= corr; O2[rr][u] *= corr; }
        }
        __syncwarp();

        // ---- P @ [V, V^2] ----
        #pragma unroll 2
        for (int j = 0; j < NT; j++) {
            const float* vrow = &Vs[j * QPAD + d0];
            float4 v0 = *(const float4*)vrow;
            float4 v1 = *(const float4*)(vrow + 4);
            float4 q0, q1;
            q0.x = v0.x * v0.x; q0.y = v0.y * v0.y; q0.z = v0.z * v0.z; q0.w = v0.w * v0.w;
            q1.x = v1.x * v1.x; q1.y = v1.y * v1.y; q1.z = v1.z * v1.z; q1.w = v1.w * v1.w;
            const float* prow = &Ps[(wid * 8) * PPAD + j];
            #pragma unroll
            for (int rr = 0; rr < 8; rr++) {
                float p = prow[rr * PPAD];
                O1[rr][0] += p * v0.x; O1[rr][1] += p * v0.y;
                O1[rr][2] += p * v0.z; O1[rr][3] += p * v0.w;
                O1[rr][4] += p * v1.x; O1[rr][5] += p * v1.y;
                O1[rr][6] += p * v1.z; O1[rr][7] += p * v1.w;
                O2[rr][0] += p * q0.x; O2[rr][1] += p * q0.y;
                O2[rr][2] += p * q0.z; O2[rr][3] += p * q0.w;
                O2[rr][4] += p * q1.x; O2[rr][5] += p * q1.y;
                O2[rr][6] += p * q1.z; O2[rr][7] += p * q1.w;
            }
        }
    }

    // ---- epilogue: mean/std/out, layout [b,c,h,w]; outputs concatenated ----
    const size_t TSZ = (size_t)NB * CH * HW;
    int boff = b * CH;
    #pragma unroll
    for (int rr = 0; rr < 8; rr++) {
        int p = p0 + wid * 8 + rr;
        float rn = 1.0f / lrow[rr];
        #pragma unroll
        for (int u = 0; u < 8; u++) {
            int c = d0 + u;
            float mean = O1[rr][u] * rn;
            float sec  = O2[rr][u] * rn;
            float var  = sec - mean * mean;
            float sd   = sqrtf(fmaxf(var, 0.f));
            size_t idx = (size_t)(boff + c) * HW + p;
            float nc = (content[idx] - g_mean[boff + c]) * g_rstd[boff + c];
            out[idx]           = sd * nc + mean;
            out[idx + TSZ]     = mean;
            out[idx + 2 * TSZ] = sd;
        }
    }
}

// =====================================================================
extern "C" void kernel_launch(void* const* d_in, const int* in_sizes, int n_in,
                              void* d_out, int out_size) {
    const float* content = (const float*)d_in[0];
    const float* style   = (const float*)d_in[1];
    const float* Wf = (const float*)d_in[2];
    const float* bf = (const float*)d_in[3];
    const float* Wg = (const float*)d_in[4];
    const float* bg = (const float*)d_in[5];
    const float* Wh = (const float*)d_in[6];
    const float* bh = (const float*)d_in[7];
    float* out = (float*)d_out;

    stats_kernel<<<2 * NBC, 256>>>(content, style);
    qkv_gemm<<<dim3(HW / 128, CH / 64, 3 * NB), 256>>>(content, style,
                                                       Wf, bf, Wg, bg, Wh, bh);
    const int smem = (MQ * QPAD + 2 * NT * QPAD + MQ * PPAD) * (int)sizeof(float);
    static bool attr_set = false;
    if (!attr_set) {
        cudaFuncSetAttribute(attn_kernel,
                             cudaFuncAttributeMaxDynamicSharedMemorySize, smem);
        attr_set = true;
    }
    attn_kernel<<<dim3(HW / MQ, NB), 256, smem>>>(content, out);
}